// round 10
// baseline (speedup 1.0000x reference)
#include <cuda_runtime.h>
#include <cuda_bf16.h>
#include <cstdint>

#define BATCH 2
#define SEQ   2048
#define DM    1024
#define NH    16
#define DH    64
#define M_TOT (BATCH*SEQ)   // 4096
#define BH_TOT (BATCH*NH)   // 32

// ---------------------------------------------------------------------------
// Scratch (__device__ globals; allocation-free rule)
// ---------------------------------------------------------------------------
__device__ __nv_bfloat16 g_xH[M_TOT*DM],  g_xL[M_TOT*DM];
__device__ __nv_bfloat16 g_WtH[3*DM*DM],  g_WtL[3*DM*DM];      // [n][k], q|k|v
__device__ __nv_bfloat16 g_WoTH[DM*DM],   g_WoTL[DM*DM];       // [n][k]
__device__ __nv_bfloat16 g_QH[BH_TOT*SEQ*DH], g_QL[BH_TOT*SEQ*DH];
__device__ __nv_bfloat16 g_KH[BH_TOT*SEQ*DH], g_KL[BH_TOT*SEQ*DH];
__device__ __nv_bfloat16 g_VtH[BH_TOT*DH*SEQ], g_VtL[BH_TOT*DH*SEQ]; // [bh][d][s]
__device__ __nv_bfloat16 g_attH[M_TOT*DM], g_attL[M_TOT*DM];
__device__ float g_rinv[BH_TOT*SEQ];

// ---------------------------------------------------------------------------
// Helpers
// ---------------------------------------------------------------------------
__device__ __forceinline__ uint32_t smem_u32(const void* p) {
    uint32_t a;
    asm("{ .reg .u64 t; cvta.to.shared.u64 t, %1; cvt.u32.u64 %0, t; }" : "=r"(a) : "l"(p));
    return a;
}
__device__ __forceinline__ void ldsm4(uint32_t* r, uint32_t a) {
    asm volatile("ldmatrix.sync.aligned.m8n8.x4.shared.b16 {%0,%1,%2,%3}, [%4];"
        : "=r"(r[0]), "=r"(r[1]), "=r"(r[2]), "=r"(r[3]) : "r"(a));
}
__device__ __forceinline__ void mma16816(float* d, const uint32_t* a, const uint32_t* b) {
    asm volatile("mma.sync.aligned.m16n8k16.row.col.f32.bf16.bf16.f32 "
        "{%0,%1,%2,%3},{%4,%5,%6,%7},{%8,%9},{%0,%1,%2,%3};"
        : "+f"(d[0]), "+f"(d[1]), "+f"(d[2]), "+f"(d[3])
        : "r"(a[0]), "r"(a[1]), "r"(a[2]), "r"(a[3]), "r"(b[0]), "r"(b[1]));
}
#define CPA16(s, g) asm volatile("cp.async.ca.shared.global [%0], [%1], 16;" :: "r"(s), "l"(g) : "memory")
#define CPA_COMMIT() asm volatile("cp.async.commit_group;" ::: "memory")
#define CPA_WAIT0()  asm volatile("cp.async.wait_group 0;" ::: "memory")
#define CPA_WAIT1()  asm volatile("cp.async.wait_group 1;" ::: "memory")
#define CPA_WAIT2()  asm volatile("cp.async.wait_group 2;" ::: "memory")
#define SWZ(o) ((o) ^ (((o) >> 3) & 0x70))

__device__ __forceinline__ void split2(float v, __nv_bfloat16& h, __nv_bfloat16& l) {
    h = __float2bfloat16(v);
    l = __float2bfloat16(v - __bfloat162float(h));
}
__device__ __forceinline__ uint32_t pack2(__nv_bfloat16 a, __nv_bfloat16 b) {
    __nv_bfloat162 t; t.x = a; t.y = b;
    return *reinterpret_cast<uint32_t*>(&t);
}
__device__ __forceinline__ uint32_t pack2f(float a, float b) {
    __nv_bfloat162 t; t.x = __float2bfloat16(a); t.y = __float2bfloat16(b);
    return *reinterpret_cast<uint32_t*>(&t);
}
__device__ __forceinline__ uint32_t pack2lo(float a, float b) {
    __nv_bfloat16 ha = __float2bfloat16(a), hb = __float2bfloat16(b);
    __nv_bfloat162 t;
    t.x = __float2bfloat16(a - __bfloat162float(ha));
    t.y = __float2bfloat16(b - __bfloat162float(hb));
    return *reinterpret_cast<uint32_t*>(&t);
}

// ---------------------------------------------------------------------------
// Prep (merged): blocks 0..4095 split x; blocks 4096..8191 transpose+split W.
// ---------------------------------------------------------------------------
__global__ void prep_kernel(const float* __restrict__ x,
                            const float* __restrict__ wq, const float* __restrict__ wk,
                            const float* __restrict__ wv, const float* __restrict__ wo) {
    __shared__ float t[32][33];
    int bx = blockIdx.x, tid = threadIdx.x;
    if (bx < 4096) {
        size_t i4 = (size_t)bx * 256 + tid;
        float4 v = *(const float4*)&x[i4 * 4];
        __nv_bfloat16 h[4], l[4];
        split2(v.x, h[0], l[0]); split2(v.y, h[1], l[1]);
        split2(v.z, h[2], l[2]); split2(v.w, h[3], l[3]);
        *(uint2*)&g_xH[i4 * 4] = *(uint2*)h;
        *(uint2*)&g_xL[i4 * 4] = *(uint2*)l;
        return;
    }
    int idx = bx - 4096;
    int which = idx >> 10; idx &= 1023;
    const float* W = (which == 0) ? wq : (which == 1) ? wk : (which == 2) ? wv : wo;
    __nv_bfloat16* H = (which < 3) ? g_WtH + (size_t)which * DM * DM : g_WoTH;
    __nv_bfloat16* L = (which < 3) ? g_WtL + (size_t)which * DM * DM : g_WoTL;
    int x0 = (idx & 31) * 32, y0 = (idx >> 5) * 32;
    int tx = tid & 31, ty = tid >> 5;
    #pragma unroll
    for (int r = 0; r < 4; r++)
        t[ty + r * 8][tx] = W[(size_t)(y0 + ty + r * 8) * DM + x0 + tx];
    __syncthreads();
    #pragma unroll
    for (int r = 0; r < 4; r++) {
        float v = t[tx][ty + r * 8];
        __nv_bfloat16 h, l; split2(v, h, l);
        size_t dst = (size_t)(x0 + ty + r * 8) * DM + y0 + tx;
        H[dst] = h; L[dst] = l;
    }
}

// ---------------------------------------------------------------------------
// Projection GEMM mainloop: 2-stage cp.async double-buffered pipeline.
// ---------------------------------------------------------------------------
#define PS_AH 0
#define PS_AL 18432
#define PS_BH 36864
#define PS_BL 55296
#define PS_STAGE 73728
#define PROJ_SMEM (2 * PS_STAGE)

__device__ __forceinline__ void proj_prefetch(uint32_t sbs,
    const __nv_bfloat16* __restrict__ Ah, const __nv_bfloat16* __restrict__ Al,
    const __nv_bfloat16* __restrict__ Bh, const __nv_bfloat16* __restrict__ Bl,
    int m0, int n0, int k0, int tid) {
    #pragma unroll
    for (int e = 0; e < 4; e++) {
        int i = tid + e * 256;
        int row = i >> 3, cc = i & 7;
        size_t ga = (size_t)(m0 + row) * DM + k0 + cc * 8;
        size_t gb = (size_t)(n0 + row) * DM + k0 + cc * 8;
        uint32_t so = sbs + row * 144 + cc * 16;
        CPA16(so + PS_AH, Ah + ga);
        CPA16(so + PS_AL, Al + ga);
        CPA16(so + PS_BH, Bh + gb);
        CPA16(so + PS_BL, Bl + gb);
    }
}

__device__ __forceinline__ void gemm_ml(char* smem,
    const __nv_bfloat16* __restrict__ Ah, const __nv_bfloat16* __restrict__ Al,
    const __nv_bfloat16* __restrict__ Bh, const __nv_bfloat16* __restrict__ Bl,
    int m0, int n0, float (&c)[2][8][4]) {
    uint32_t sb0 = smem_u32(smem);
    int tid = threadIdx.x, lane = tid & 31, w = tid >> 5;
    int wm = (w >> 1) * 32, wn = (w & 1) * 64;

    proj_prefetch(sb0, Ah, Al, Bh, Bl, m0, n0, 0, tid);
    CPA_COMMIT();

    for (int s = 0; s < 16; s++) {
        if (s + 1 < 16) {
            proj_prefetch(sb0 + ((s + 1) & 1) * PS_STAGE, Ah, Al, Bh, Bl,
                          m0, n0, (s + 1) * 64, tid);
            CPA_COMMIT();
            CPA_WAIT1();
        } else {
            CPA_WAIT0();
        }
        __syncthreads();
        uint32_t sb = sb0 + (s & 1) * PS_STAGE;
        #pragma unroll
        for (int ks = 0; ks < 64; ks += 16) {
            uint32_t ah[2][4], al[2][4], bhf[8][2], blf[8][2];
            #pragma unroll
            for (int mt = 0; mt < 2; mt++) {
                uint32_t ad = sb + PS_AH + (uint32_t)(wm + mt * 16 + (lane & 15)) * 144
                            + (ks + (lane >> 4) * 8) * 2;
                ldsm4(ah[mt], ad);
                ldsm4(al[mt], ad + (PS_AL - PS_AH));
            }
            #pragma unroll
            for (int nt2 = 0; nt2 < 4; nt2++) {
                uint32_t bd = sb + PS_BH
                            + (uint32_t)(wn + nt2 * 16 + ((lane >> 4) << 3) + (lane & 7)) * 144
                            + (ks + ((lane >> 3) & 1) * 8) * 2;
                uint32_t t[4];
                ldsm4(t, bd);
                bhf[nt2*2][0]=t[0]; bhf[nt2*2][1]=t[1]; bhf[nt2*2+1][0]=t[2]; bhf[nt2*2+1][1]=t[3];
                ldsm4(t, bd + (PS_BL - PS_BH));
                blf[nt2*2][0]=t[0]; blf[nt2*2][1]=t[1]; blf[nt2*2+1][0]=t[2]; blf[nt2*2+1][1]=t[3];
            }
            #pragma unroll
            for (int mt = 0; mt < 2; mt++)
                #pragma unroll
                for (int nt = 0; nt < 8; nt++) {
                    mma16816(c[mt][nt], ah[mt], bhf[nt]);
                    mma16816(c[mt][nt], ah[mt], blf[nt]);
                    mma16816(c[mt][nt], al[mt], bhf[nt]);
                }
        }
        __syncthreads();
    }
}

// ---------------------------------------------------------------------------
// QKV projection
// ---------------------------------------------------------------------------
__global__ void __launch_bounds__(256, 1) proj_qkv_kernel(
    const float* __restrict__ bq, const float* __restrict__ bk, const float* __restrict__ bv) {
    extern __shared__ char smem[];
    int n0 = blockIdx.x * 128;
    int m0 = blockIdx.y * 128;
    float c[2][8][4] = {};
    gemm_ml(smem, g_xH, g_xL, g_WtH, g_WtL, m0, n0, c);

    int tid = threadIdx.x, lane = tid & 31, w = tid >> 5;
    int wm = (w >> 1) * 32, wn = (w & 1) * 64;
    int gid = lane >> 2, tid4 = lane & 3;
    int j = n0 >> 10, nb = n0 & 1023;
    const float* bias = (j == 0) ? bq : (j == 1) ? bk : bv;
    float scale = (j == 0) ? 0.125f : 1.0f;
    __nv_bfloat16* dH = (j == 0) ? g_QH : g_KH;
    __nv_bfloat16* dL = (j == 0) ? g_QL : g_KL;

    #pragma unroll
    for (int mt = 0; mt < 2; mt++)
        #pragma unroll
        for (int rh = 0; rh < 2; rh++) {
            int m = m0 + wm + mt * 16 + rh * 8 + gid;
            int b = m >> 11, s2 = m & (SEQ - 1);
            #pragma unroll
            for (int nt = 0; nt < 8; nt++) {
                int nl = nb + wn + nt * 8 + tid4 * 2;
                float v0 = (c[mt][nt][rh * 2 + 0] + bias[nl]) * scale;
                float v1 = (c[mt][nt][rh * 2 + 1] + bias[nl + 1]) * scale;
                __nv_bfloat16 h0, l0, h1, l1;
                split2(v0, h0, l0); split2(v1, h1, l1);
                int hh = nl >> 6, d = nl & 63;
                if (j < 2) {
                    size_t dst = (((size_t)(b * NH + hh)) * SEQ + s2) * DH + d;
                    *(uint32_t*)&dH[dst] = pack2(h0, h1);
                    *(uint32_t*)&dL[dst] = pack2(l0, l1);
                } else {
                    size_t dst = (((size_t)(b * NH + hh)) * DH + d) * SEQ + s2;
                    g_VtH[dst] = h0; g_VtH[dst + SEQ] = h1;
                    g_VtL[dst] = l0; g_VtL[dst + SEQ] = l1;
                }
            }
        }
}

// ---------------------------------------------------------------------------
// Output projection (standalone)
// ---------------------------------------------------------------------------
__global__ void __launch_bounds__(256, 1) proj_o_kernel(
    const float* __restrict__ bo, float* __restrict__ out) {
    extern __shared__ char smem[];
    int n0 = blockIdx.x * 128;
    int m0 = blockIdx.y * 128;
    float c[2][8][4] = {};
    gemm_ml(smem, g_attH, g_attL, g_WoTH, g_WoTL, m0, n0, c);

    int tid = threadIdx.x, lane = tid & 31, w = tid >> 5;
    int wm = (w >> 1) * 32, wn = (w & 1) * 64;
    int gid = lane >> 2, tid4 = lane & 3;

    #pragma unroll
    for (int mt = 0; mt < 2; mt++)
        #pragma unroll
        for (int rh = 0; rh < 2; rh++) {
            int m = m0 + wm + mt * 16 + rh * 8 + gid;
            #pragma unroll
            for (int nt = 0; nt < 8; nt++) {
                int n = n0 + wn + nt * 8 + tid4 * 2;
                float2 o;
                o.x = c[mt][nt][rh * 2 + 0] + bo[n];
                o.y = c[mt][nt][rh * 2 + 1] + bo[n + 1];
                *(float2*)&out[(size_t)m * DM + n] = o;
            }
        }
}

// ---------------------------------------------------------------------------
// Attention: q-tile 128, 512 threads (16 warps = 8m x 2n), register-E,
// swizzled smem, K double-buffered cp.async, V single-buffered cp.async.
// ---------------------------------------------------------------------------
#define AQ_H 0
#define AQ_L 16384
#define AK   32768            /* buf b: AK + b*32768 ; lo at +16384 */
#define AV_H 98304
#define AV_L 114688
#define ARED 131072
#define ARINV 132096
#define ATTN_SMEM 132608

__device__ __forceinline__ uint32_t vswz(int vr, int c16) {
    return (uint32_t)(vr * 256 + ((c16 ^ ((vr & 7) << 1)) << 4));
}

__device__ __forceinline__ void attn_load_K(uint32_t kb, int bh, int kt, int tid) {
    #pragma unroll
    for (int e = 0; e < 2; e++) {
        int i = tid + e * 512;
        int row = i >> 3, c = i & 7;
        size_t g = ((size_t)bh * SEQ + kt * 128 + row) * DH + c * 8;
        uint32_t sw = SWZ((uint32_t)(row * 128 + c * 16));
        CPA16(kb + sw, g_KH + g);
        CPA16(kb + 16384 + sw, g_KL + g);
    }
}
__device__ __forceinline__ void attn_load_V(uint32_t sb, int bh, int kt, int tid) {
    #pragma unroll
    for (int e = 0; e < 2; e++) {
        int i = tid + e * 512;
        int vr = i >> 4, c16 = i & 15;
        size_t g = ((size_t)bh * DH + vr) * SEQ + kt * 128 + c16 * 8;
        uint32_t sw = vswz(vr, c16);
        CPA16(sb + AV_H + sw, g_VtH + g);
        CPA16(sb + AV_L + sw, g_VtL + g);
    }
}

__global__ void __launch_bounds__(512, 1) attn_tc_kernel(float* __restrict__ weights) {
    extern __shared__ char smem[];
    uint32_t sb = smem_u32(smem);
    int tid = threadIdx.x, lane = tid & 31, w = tid >> 5;
    int wm = (w >> 1) * 16;          // 8 m-groups x 16 rows = 128 q rows
    int wn = (w & 1) * 64;           // 2 k-column slices
    int gid = lane >> 2, tid4 = lane & 3;
    int bh = blockIdx.y, q0 = blockIdx.x * 128;

    // preload Q + K(0)
    #pragma unroll
    for (int e = 0; e < 2; e++) {
        int i = tid + e * 512;
        int row = i >> 3, c = i & 7;
        size_t g = ((size_t)bh * SEQ + q0 + row) * DH + c * 8;
        uint32_t sw = SWZ((uint32_t)(row * 128 + c * 16));
        CPA16(sb + AQ_H + sw, g_QH + g);
        CPA16(sb + AQ_L + sw, g_QL + g);
    }
    attn_load_K(sb + AK, bh, 0, tid);
    CPA_COMMIT();

    float* wbase = weights + (size_t)bh * SEQ * SEQ;
    float pv[8][4] = {};
    float rsum[2] = {};

    for (int kt = 0; kt < SEQ / 128; kt++) {
        __syncthreads();                         // V buf free, K buf reusable
        attn_load_V(sb, bh, kt, tid);
        CPA_COMMIT();                            // group GV(kt)
        if (kt + 1 < SEQ / 128) {
            attn_load_K(sb + AK + ((kt + 1) & 1) * 32768, bh, kt + 1, tid);
            CPA_COMMIT();                        // group GK(kt)
            CPA_WAIT2();                         // K(kt) (older groups) arrived
        } else {
            CPA_WAIT1();                         // only GV(15) may pend
        }
        __syncthreads();

        uint32_t kbuf = sb + AK + (kt & 1) * 32768;

        // ---- S = Q K^T ----
        float s[8][4] = {};
        #pragma unroll
        for (int ks = 0; ks < 64; ks += 16) {
            uint32_t ah[4], al[4], bhf[8][2], blf[8][2];
            uint32_t offA = (uint32_t)((wm + (lane & 15)) * 128 + (ks + (lane >> 4) * 8) * 2);
            uint32_t ad = sb + AQ_H + SWZ(offA);
            ldsm4(ah, ad);
            ldsm4(al, ad + 16384);
            #pragma unroll
            for (int nt2 = 0; nt2 < 4; nt2++) {
                uint32_t offB = (uint32_t)((wn + nt2 * 16 + ((lane >> 4) << 3) + (lane & 7)) * 128
                              + (ks + ((lane >> 3) & 1) * 8) * 2);
                uint32_t bd = kbuf + SWZ(offB);
                uint32_t t[4];
                ldsm4(t, bd);
                bhf[nt2*2][0]=t[0]; bhf[nt2*2][1]=t[1]; bhf[nt2*2+1][0]=t[2]; bhf[nt2*2+1][1]=t[3];
                ldsm4(t, bd + 16384);
                blf[nt2*2][0]=t[0]; blf[nt2*2][1]=t[1]; blf[nt2*2+1][0]=t[2]; blf[nt2*2+1][1]=t[3];
            }
            #pragma unroll
            for (int nt = 0; nt < 8; nt++) {
                mma16816(s[nt], ah, bhf[nt]);
                mma16816(s[nt], ah, blf[nt]);
                mma16816(s[nt], al, bhf[nt]);
            }
        }

        // ---- exp in regs, rowsum, unnormalized weights store ----
        int row0 = q0 + wm + gid;
        #pragma unroll
        for (int nt = 0; nt < 8; nt++) {
            s[nt][0] = __expf(s[nt][0]);
            s[nt][1] = __expf(s[nt][1]);
            s[nt][2] = __expf(s[nt][2]);
            s[nt][3] = __expf(s[nt][3]);
            rsum[0] += s[nt][0] + s[nt][1];
            rsum[1] += s[nt][2] + s[nt][3];
            int col = kt * 128 + wn + nt * 8 + tid4 * 2;
            *(float2*)&wbase[(size_t)row0 * SEQ + col]       = make_float2(s[nt][0], s[nt][1]);
            *(float2*)&wbase[(size_t)(row0 + 8) * SEQ + col] = make_float2(s[nt][2], s[nt][3]);
        }

        if (kt + 1 < SEQ / 128) { CPA_WAIT1(); } else { CPA_WAIT0(); }  // V(kt) arrived
        __syncthreads();

        // ---- pv += E(this warp's k-slice) x V ----
        #pragma unroll
        for (int j = 0; j < 4; j++) {
            uint32_t eh[4], el[4];
            eh[0] = pack2f (s[2*j][0],   s[2*j][1]);
            eh[1] = pack2f (s[2*j][2],   s[2*j][3]);
            eh[2] = pack2f (s[2*j+1][0], s[2*j+1][1]);
            eh[3] = pack2f (s[2*j+1][2], s[2*j+1][3]);
            el[0] = pack2lo(s[2*j][0],   s[2*j][1]);
            el[1] = pack2lo(s[2*j][2],   s[2*j][3]);
            el[2] = pack2lo(s[2*j+1][0], s[2*j+1][1]);
            el[3] = pack2lo(s[2*j+1][2], s[2*j+1][3]);

            uint32_t vh[8][2], vl[8][2];
            #pragma unroll
            for (int dt2 = 0; dt2 < 4; dt2++) {
                int vr = dt2 * 16 + ((lane >> 4) << 3) + (lane & 7);
                int c16 = (wn * 2 + j * 32 + ((lane >> 3) & 1) * 16) >> 4;
                uint32_t vad = sb + AV_H + vswz(vr, c16);
                uint32_t t[4];
                ldsm4(t, vad);
                vh[dt2*2][0]=t[0]; vh[dt2*2][1]=t[1]; vh[dt2*2+1][0]=t[2]; vh[dt2*2+1][1]=t[3];
                ldsm4(t, vad + 16384);
                vl[dt2*2][0]=t[0]; vl[dt2*2][1]=t[1]; vl[dt2*2+1][0]=t[2]; vl[dt2*2+1][1]=t[3];
            }
            #pragma unroll
            for (int nt = 0; nt < 8; nt++) {
                mma16816(pv[nt], eh, vh[nt]);
                mma16816(pv[nt], eh, vl[nt]);
                mma16816(pv[nt], el, vh[nt]);
            }
        }
    }
    __syncthreads();

    // ---- rowsum reduce ----
    float* red   = (float*)(smem + ARED);    // [128][2]
    float* rinvs = (float*)(smem + ARINV);   // [128]
    float* xch   = (float*)(smem + AK);      // reuse K region: 8 warps x 32 x 32 floats
    #pragma unroll
    for (int i = 0; i < 2; i++) {
        rsum[i] += __shfl_xor_sync(0xFFFFFFFFu, rsum[i], 1);
        rsum[i] += __shfl_xor_sync(0xFFFFFFFFu, rsum[i], 2);
    }
    if (tid4 == 0) {
        red[(wm + 0 + gid) * 2 + (w & 1)] = rsum[0];
        red[(wm + 8 + gid) * 2 + (w & 1)] = rsum[1];
    }
    if (w & 1) {
        #pragma unroll
        for (int nt = 0; nt < 8; nt++)
            #pragma unroll
            for (int i = 0; i < 4; i++)
                xch[((w >> 1) * 32 + lane) * 32 + nt * 4 + i] = pv[nt][i];
    }
    __syncthreads();
    if (tid < 128) {
        float ri = 1.0f / (red[tid * 2] + red[tid * 2 + 1]);
        rinvs[tid] = ri;
        g_rinv[(size_t)bh * SEQ + q0 + tid] = ri;
    }
    __syncthreads();

    if (!(w & 1)) {
        #pragma unroll
        for (int nt = 0; nt < 8; nt++)
            #pragma unroll
            for (int i = 0; i < 4; i++)
                pv[nt][i] += xch[((w >> 1) * 32 + lane) * 32 + nt * 4 + i];

        int b = bh >> 4, h = bh & 15;
        #pragma unroll
        for (int rh = 0; rh < 2; rh++) {
            int row = wm + rh * 8 + gid;
            float ri = rinvs[row];
            #pragma unroll
            for (int nt = 0; nt < 8; nt++) {
                float v0 = pv[nt][rh * 2 + 0] * ri;
                float v1 = pv[nt][rh * 2 + 1] * ri;
                int d = nt * 8 + tid4 * 2;
                __nv_bfloat16 h0, l0, h1, l1;
                split2(v0, h0, l0); split2(v1, h1, l1);
                size_t dst = ((size_t)(b * SEQ + q0 + row)) * DM + h * DH + d;
                *(uint32_t*)&g_attH[dst] = pack2(h0, h1);
                *(uint32_t*)&g_attL[dst] = pack2(l0, l1);
            }
        }
    }
}

// ---------------------------------------------------------------------------
// Normalize weights in place (streaming)
// ---------------------------------------------------------------------------
__global__ void norm_kernel(float* __restrict__ w) {
    size_t f4 = (size_t)blockIdx.x * blockDim.x + threadIdx.x;
    size_t fidx = f4 * 4;
    int rowi = (int)(fidx >> 11);
    float r = g_rinv[rowi];
    float4 v = *(float4*)&w[fidx];
    v.x *= r; v.y *= r; v.z *= r; v.w *= r;
    *(float4*)&w[fidx] = v;
}

// ---------------------------------------------------------------------------
extern "C" void kernel_launch(void* const* d_in, const int* in_sizes, int n_in,
                              void* d_out, int out_size) {
    const float* x  = (const float*)d_in[0];
    const float* wq = (const float*)d_in[1];
    const float* bq = (const float*)d_in[2];
    const float* wk = (const float*)d_in[3];
    const float* bk = (const float*)d_in[4];
    const float* wv = (const float*)d_in[5];
    const float* bv = (const float*)d_in[6];
    const float* wo = (const float*)d_in[7];
    const float* bo = (const float*)d_in[8];

    float* out     = (float*)d_out;
    float* weights = out + (size_t)M_TOT * DM;

    static cudaStream_t s2 = nullptr;
    static cudaEvent_t evFork = nullptr, evJoin = nullptr;
    if (!s2) {
        cudaStreamCreateWithFlags(&s2, cudaStreamNonBlocking);
        cudaEventCreateWithFlags(&evFork, cudaEventDisableTiming);
        cudaEventCreateWithFlags(&evJoin, cudaEventDisableTiming);
        cudaFuncSetAttribute(proj_qkv_kernel, cudaFuncAttributeMaxDynamicSharedMemorySize, PROJ_SMEM);
        cudaFuncSetAttribute(proj_o_kernel,   cudaFuncAttributeMaxDynamicSharedMemorySize, PROJ_SMEM);
        cudaFuncSetAttribute(attn_tc_kernel,  cudaFuncAttributeMaxDynamicSharedMemorySize, ATTN_SMEM);
    }

    prep_kernel<<<8192, 256>>>(x, wq, wk, wv, wo);

    proj_qkv_kernel<<<dim3(3 * DM / 128, M_TOT / 128), 256, PROJ_SMEM>>>(bq, bk, bv);

    attn_tc_kernel<<<dim3(SEQ / 128, BH_TOT), 512, ATTN_SMEM>>>(weights);

    // Fork: norm (DRAM-bound) concurrent with proj_o (tensor-bound)
    cudaEventRecord(evFork, 0);
    cudaStreamWaitEvent(s2, evFork, 0);

    size_t nf4 = (size_t)BH_TOT * SEQ * SEQ / 4;
    norm_kernel<<<(unsigned)(nf4 / 256), 256, 0, s2>>>(weights);

    proj_o_kernel<<<dim3(DM / 128, M_TOT / 128), 256, PROJ_SMEM>>>(bo, out);

    cudaEventRecord(evJoin, s2);
    cudaStreamWaitEvent(0, evJoin, 0);
}

// round 11
// speedup vs baseline: 1.0038x; 1.0038x over previous
#include <cuda_runtime.h>
#include <cuda_bf16.h>
#include <cstdint>

#define BATCH 2
#define SEQ   2048
#define DM    1024
#define NH    16
#define DH    64
#define M_TOT (BATCH*SEQ)   // 4096
#define BH_TOT (BATCH*NH)   // 32

// ---------------------------------------------------------------------------
// Scratch (__device__ globals; allocation-free rule)
// ---------------------------------------------------------------------------
__device__ __nv_bfloat16 g_xH[M_TOT*DM],  g_xL[M_TOT*DM];
__device__ __nv_bfloat16 g_WtH[3*DM*DM],  g_WtL[3*DM*DM];      // [n][k], q|k|v
__device__ __nv_bfloat16 g_WoTH[DM*DM],   g_WoTL[DM*DM];       // [n][k]
__device__ __nv_bfloat16 g_QH[BH_TOT*SEQ*DH], g_QL[BH_TOT*SEQ*DH];
__device__ __nv_bfloat16 g_KH[BH_TOT*SEQ*DH], g_KL[BH_TOT*SEQ*DH];
__device__ __nv_bfloat16 g_VtH[BH_TOT*DH*SEQ], g_VtL[BH_TOT*DH*SEQ]; // [bh][d][s]
__device__ __nv_bfloat16 g_attH[M_TOT*DM], g_attL[M_TOT*DM];
__device__ float g_rinv[BH_TOT*SEQ];

// ---------------------------------------------------------------------------
// Helpers
// ---------------------------------------------------------------------------
__device__ __forceinline__ uint32_t smem_u32(const void* p) {
    uint32_t a;
    asm("{ .reg .u64 t; cvta.to.shared.u64 t, %1; cvt.u32.u64 %0, t; }" : "=r"(a) : "l"(p));
    return a;
}
__device__ __forceinline__ void ldsm4(uint32_t* r, uint32_t a) {
    asm volatile("ldmatrix.sync.aligned.m8n8.x4.shared.b16 {%0,%1,%2,%3}, [%4];"
        : "=r"(r[0]), "=r"(r[1]), "=r"(r[2]), "=r"(r[3]) : "r"(a));
}
__device__ __forceinline__ void mma16816(float* d, const uint32_t* a, const uint32_t* b) {
    asm volatile("mma.sync.aligned.m16n8k16.row.col.f32.bf16.bf16.f32 "
        "{%0,%1,%2,%3},{%4,%5,%6,%7},{%8,%9},{%0,%1,%2,%3};"
        : "+f"(d[0]), "+f"(d[1]), "+f"(d[2]), "+f"(d[3])
        : "r"(a[0]), "r"(a[1]), "r"(a[2]), "r"(a[3]), "r"(b[0]), "r"(b[1]));
}
#define CPA16(s, g) asm volatile("cp.async.ca.shared.global [%0], [%1], 16;" :: "r"(s), "l"(g) : "memory")
#define CPA_COMMIT() asm volatile("cp.async.commit_group;" ::: "memory")
#define CPA_WAIT0()  asm volatile("cp.async.wait_group 0;" ::: "memory")
#define CPA_WAIT1()  asm volatile("cp.async.wait_group 1;" ::: "memory")
#define SWZ(o) ((o) ^ (((o) >> 3) & 0x70))

__device__ __forceinline__ void split2(float v, __nv_bfloat16& h, __nv_bfloat16& l) {
    h = __float2bfloat16(v);
    l = __float2bfloat16(v - __bfloat162float(h));
}
__device__ __forceinline__ uint32_t pack2(__nv_bfloat16 a, __nv_bfloat16 b) {
    __nv_bfloat162 t; t.x = a; t.y = b;
    return *reinterpret_cast<uint32_t*>(&t);
}
__device__ __forceinline__ uint32_t pack2f(float a, float b) {
    __nv_bfloat162 t; t.x = __float2bfloat16(a); t.y = __float2bfloat16(b);
    return *reinterpret_cast<uint32_t*>(&t);
}
__device__ __forceinline__ uint32_t pack2lo(float a, float b) {
    __nv_bfloat16 ha = __float2bfloat16(a), hb = __float2bfloat16(b);
    __nv_bfloat162 t;
    t.x = __float2bfloat16(a - __bfloat162float(ha));
    t.y = __float2bfloat16(b - __bfloat162float(hb));
    return *reinterpret_cast<uint32_t*>(&t);
}

// ---------------------------------------------------------------------------
// Prep (merged): blocks 0..4095 split x; blocks 4096..8191 transpose+split W.
// ---------------------------------------------------------------------------
__global__ void prep_kernel(const float* __restrict__ x,
                            const float* __restrict__ wq, const float* __restrict__ wk,
                            const float* __restrict__ wv, const float* __restrict__ wo) {
    __shared__ float t[32][33];
    int bx = blockIdx.x, tid = threadIdx.x;
    if (bx < 4096) {
        size_t i4 = (size_t)bx * 256 + tid;
        float4 v = *(const float4*)&x[i4 * 4];
        __nv_bfloat16 h[4], l[4];
        split2(v.x, h[0], l[0]); split2(v.y, h[1], l[1]);
        split2(v.z, h[2], l[2]); split2(v.w, h[3], l[3]);
        *(uint2*)&g_xH[i4 * 4] = *(uint2*)h;
        *(uint2*)&g_xL[i4 * 4] = *(uint2*)l;
        return;
    }
    int idx = bx - 4096;
    int which = idx >> 10; idx &= 1023;
    const float* W = (which == 0) ? wq : (which == 1) ? wk : (which == 2) ? wv : wo;
    __nv_bfloat16* H = (which < 3) ? g_WtH + (size_t)which * DM * DM : g_WoTH;
    __nv_bfloat16* L = (which < 3) ? g_WtL + (size_t)which * DM * DM : g_WoTL;
    int x0 = (idx & 31) * 32, y0 = (idx >> 5) * 32;
    int tx = tid & 31, ty = tid >> 5;
    #pragma unroll
    for (int r = 0; r < 4; r++)
        t[ty + r * 8][tx] = W[(size_t)(y0 + ty + r * 8) * DM + x0 + tx];
    __syncthreads();
    #pragma unroll
    for (int r = 0; r < 4; r++) {
        float v = t[tx][ty + r * 8];
        __nv_bfloat16 h, l; split2(v, h, l);
        size_t dst = (size_t)(x0 + ty + r * 8) * DM + y0 + tx;
        H[dst] = h; L[dst] = l;
    }
}

// ---------------------------------------------------------------------------
// Projection GEMM mainloop: 2-stage cp.async double-buffered pipeline.
// ---------------------------------------------------------------------------
#define PS_AH 0
#define PS_AL 18432
#define PS_BH 36864
#define PS_BL 55296
#define PS_STAGE 73728
#define PROJ_SMEM (2 * PS_STAGE)

__device__ __forceinline__ void proj_prefetch(uint32_t sbs,
    const __nv_bfloat16* __restrict__ Ah, const __nv_bfloat16* __restrict__ Al,
    const __nv_bfloat16* __restrict__ Bh, const __nv_bfloat16* __restrict__ Bl,
    int m0, int n0, int k0, int tid) {
    #pragma unroll
    for (int e = 0; e < 4; e++) {
        int i = tid + e * 256;
        int row = i >> 3, cc = i & 7;
        size_t ga = (size_t)(m0 + row) * DM + k0 + cc * 8;
        size_t gb = (size_t)(n0 + row) * DM + k0 + cc * 8;
        uint32_t so = sbs + row * 144 + cc * 16;
        CPA16(so + PS_AH, Ah + ga);
        CPA16(so + PS_AL, Al + ga);
        CPA16(so + PS_BH, Bh + gb);
        CPA16(so + PS_BL, Bl + gb);
    }
}

__device__ __forceinline__ void gemm_ml(char* smem,
    const __nv_bfloat16* __restrict__ Ah, const __nv_bfloat16* __restrict__ Al,
    const __nv_bfloat16* __restrict__ Bh, const __nv_bfloat16* __restrict__ Bl,
    int m0, int n0, float (&c)[2][8][4]) {
    uint32_t sb0 = smem_u32(smem);
    int tid = threadIdx.x, lane = tid & 31, w = tid >> 5;
    int wm = (w >> 1) * 32, wn = (w & 1) * 64;

    proj_prefetch(sb0, Ah, Al, Bh, Bl, m0, n0, 0, tid);
    CPA_COMMIT();

    for (int s = 0; s < 16; s++) {
        if (s + 1 < 16) {
            proj_prefetch(sb0 + ((s + 1) & 1) * PS_STAGE, Ah, Al, Bh, Bl,
                          m0, n0, (s + 1) * 64, tid);
            CPA_COMMIT();
            CPA_WAIT1();
        } else {
            CPA_WAIT0();
        }
        __syncthreads();
        uint32_t sb = sb0 + (s & 1) * PS_STAGE;
        #pragma unroll
        for (int ks = 0; ks < 64; ks += 16) {
            uint32_t ah[2][4], al[2][4], bhf[8][2], blf[8][2];
            #pragma unroll
            for (int mt = 0; mt < 2; mt++) {
                uint32_t ad = sb + PS_AH + (uint32_t)(wm + mt * 16 + (lane & 15)) * 144
                            + (ks + (lane >> 4) * 8) * 2;
                ldsm4(ah[mt], ad);
                ldsm4(al[mt], ad + (PS_AL - PS_AH));
            }
            #pragma unroll
            for (int nt2 = 0; nt2 < 4; nt2++) {
                uint32_t bd = sb + PS_BH
                            + (uint32_t)(wn + nt2 * 16 + ((lane >> 4) << 3) + (lane & 7)) * 144
                            + (ks + ((lane >> 3) & 1) * 8) * 2;
                uint32_t t[4];
                ldsm4(t, bd);
                bhf[nt2*2][0]=t[0]; bhf[nt2*2][1]=t[1]; bhf[nt2*2+1][0]=t[2]; bhf[nt2*2+1][1]=t[3];
                ldsm4(t, bd + (PS_BL - PS_BH));
                blf[nt2*2][0]=t[0]; blf[nt2*2][1]=t[1]; blf[nt2*2+1][0]=t[2]; blf[nt2*2+1][1]=t[3];
            }
            #pragma unroll
            for (int mt = 0; mt < 2; mt++)
                #pragma unroll
                for (int nt = 0; nt < 8; nt++) {
                    mma16816(c[mt][nt], ah[mt], bhf[nt]);
                    mma16816(c[mt][nt], ah[mt], blf[nt]);
                    mma16816(c[mt][nt], al[mt], bhf[nt]);
                }
        }
        __syncthreads();
    }
}

// ---------------------------------------------------------------------------
// QKV projection
// ---------------------------------------------------------------------------
__global__ void __launch_bounds__(256, 1) proj_qkv_kernel(
    const float* __restrict__ bq, const float* __restrict__ bk, const float* __restrict__ bv) {
    extern __shared__ char smem[];
    int n0 = blockIdx.x * 128;
    int m0 = blockIdx.y * 128;
    float c[2][8][4] = {};
    gemm_ml(smem, g_xH, g_xL, g_WtH, g_WtL, m0, n0, c);

    int tid = threadIdx.x, lane = tid & 31, w = tid >> 5;
    int wm = (w >> 1) * 32, wn = (w & 1) * 64;
    int gid = lane >> 2, tid4 = lane & 3;
    int j = n0 >> 10, nb = n0 & 1023;
    const float* bias = (j == 0) ? bq : (j == 1) ? bk : bv;
    float scale = (j == 0) ? 0.125f : 1.0f;
    __nv_bfloat16* dH = (j == 0) ? g_QH : g_KH;
    __nv_bfloat16* dL = (j == 0) ? g_QL : g_KL;

    #pragma unroll
    for (int mt = 0; mt < 2; mt++)
        #pragma unroll
        for (int rh = 0; rh < 2; rh++) {
            int m = m0 + wm + mt * 16 + rh * 8 + gid;
            int b = m >> 11, s2 = m & (SEQ - 1);
            #pragma unroll
            for (int nt = 0; nt < 8; nt++) {
                int nl = nb + wn + nt * 8 + tid4 * 2;
                float v0 = (c[mt][nt][rh * 2 + 0] + bias[nl]) * scale;
                float v1 = (c[mt][nt][rh * 2 + 1] + bias[nl + 1]) * scale;
                __nv_bfloat16 h0, l0, h1, l1;
                split2(v0, h0, l0); split2(v1, h1, l1);
                int hh = nl >> 6, d = nl & 63;
                if (j < 2) {
                    size_t dst = (((size_t)(b * NH + hh)) * SEQ + s2) * DH + d;
                    *(uint32_t*)&dH[dst] = pack2(h0, h1);
                    *(uint32_t*)&dL[dst] = pack2(l0, l1);
                } else {
                    size_t dst = (((size_t)(b * NH + hh)) * DH + d) * SEQ + s2;
                    g_VtH[dst] = h0; g_VtH[dst + SEQ] = h1;
                    g_VtL[dst] = l0; g_VtL[dst + SEQ] = l1;
                }
            }
        }
}

// ---------------------------------------------------------------------------
// Output projection (standalone)
// ---------------------------------------------------------------------------
__global__ void __launch_bounds__(256, 1) proj_o_kernel(
    const float* __restrict__ bo, float* __restrict__ out) {
    extern __shared__ char smem[];
    int n0 = blockIdx.x * 128;
    int m0 = blockIdx.y * 128;
    float c[2][8][4] = {};
    gemm_ml(smem, g_attH, g_attL, g_WoTH, g_WoTL, m0, n0, c);

    int tid = threadIdx.x, lane = tid & 31, w = tid >> 5;
    int wm = (w >> 1) * 32, wn = (w & 1) * 64;
    int gid = lane >> 2, tid4 = lane & 3;

    #pragma unroll
    for (int mt = 0; mt < 2; mt++)
        #pragma unroll
        for (int rh = 0; rh < 2; rh++) {
            int m = m0 + wm + mt * 16 + rh * 8 + gid;
            #pragma unroll
            for (int nt = 0; nt < 8; nt++) {
                int n = n0 + wn + nt * 8 + tid4 * 2;
                float2 o;
                o.x = c[mt][nt][rh * 2 + 0] + bo[n];
                o.y = c[mt][nt][rh * 2 + 1] + bo[n + 1];
                *(float2*)&out[(size_t)m * DM + n] = o;
            }
        }
}

// ---------------------------------------------------------------------------
// Attention: q-tile 128, 512 threads (16 warps = 8m x 2n), register-E.
// K AND V double-buffered; ONE barrier per kt; prefetch issued right after
// the barrier so it has the whole iteration's compute to land.
// ---------------------------------------------------------------------------
#define AQ_H 0                /* Q hi 16KB, lo at +16384 */
#define AKB  32768            /* K buf b: AKB + b*32768 (hi), +16384 (lo) */
#define AVB  98304            /* V buf b: AVB + b*32768 (hi), +16384 (lo) */
#define ARED 163840
#define ARINV 164864
#define ATTN_SMEM 165376

__device__ __forceinline__ uint32_t vswz(int vr, int c16) {
    return (uint32_t)(vr * 256 + ((c16 ^ ((vr & 7) << 1)) << 4));
}

__device__ __forceinline__ void attn_load_KV(uint32_t sb, int buf, int bh, int kt, int tid) {
    uint32_t kb = sb + AKB + buf * 32768;
    uint32_t vb = sb + AVB + buf * 32768;
    #pragma unroll
    for (int e = 0; e < 2; e++) {
        int i = tid + e * 512;
        int row = i >> 3, c = i & 7;
        size_t g = ((size_t)bh * SEQ + kt * 128 + row) * DH + c * 8;
        uint32_t sw = SWZ((uint32_t)(row * 128 + c * 16));
        CPA16(kb + sw, g_KH + g);
        CPA16(kb + 16384 + sw, g_KL + g);
    }
    #pragma unroll
    for (int e = 0; e < 2; e++) {
        int i = tid + e * 512;
        int vr = i >> 4, c16 = i & 15;
        size_t g = ((size_t)bh * DH + vr) * SEQ + kt * 128 + c16 * 8;
        uint32_t sw = vswz(vr, c16);
        CPA16(vb + sw, g_VtH + g);
        CPA16(vb + 16384 + sw, g_VtL + g);
    }
}

__global__ void __launch_bounds__(512, 1) attn_tc_kernel(float* __restrict__ weights) {
    extern __shared__ char smem[];
    uint32_t sb = smem_u32(smem);
    int tid = threadIdx.x, lane = tid & 31, w = tid >> 5;
    int wm = (w >> 1) * 16;          // 8 m-groups x 16 rows = 128 q rows
    int wn = (w & 1) * 64;           // 2 k-column slices
    int gid = lane >> 2, tid4 = lane & 3;
    int bh = blockIdx.y, q0 = blockIdx.x * 128;

    // preload Q + K/V(0) in one group
    #pragma unroll
    for (int e = 0; e < 2; e++) {
        int i = tid + e * 512;
        int row = i >> 3, c = i & 7;
        size_t g = ((size_t)bh * SEQ + q0 + row) * DH + c * 8;
        uint32_t sw = SWZ((uint32_t)(row * 128 + c * 16));
        CPA16(sb + AQ_H + sw, g_QH + g);
        CPA16(sb + AQ_H + 16384 + sw, g_QL + g);
    }
    attn_load_KV(sb, 0, bh, 0, tid);
    CPA_COMMIT();

    float* wbase = weights + (size_t)bh * SEQ * SEQ;
    float pv[8][4] = {};
    float rsum[2] = {};

    for (int kt = 0; kt < SEQ / 128; kt++) {
        CPA_WAIT0();                 // G(kt) fully arrived (per-thread)
        __syncthreads();             // all threads' pieces visible; prev compute done
        if (kt + 1 < SEQ / 128) {
            attn_load_KV(sb, (kt + 1) & 1, bh, kt + 1, tid);
            CPA_COMMIT();            // lands during this iteration's compute
        }
        uint32_t kbuf = sb + AKB + (kt & 1) * 32768;
        uint32_t vbuf = sb + AVB + (kt & 1) * 32768;

        // ---- S = Q K^T (scale pre-folded into Q) ----
        float s[8][4] = {};
        #pragma unroll
        for (int ks = 0; ks < 64; ks += 16) {
            uint32_t ah[4], al[4], bhf[8][2], blf[8][2];
            uint32_t offA = (uint32_t)((wm + (lane & 15)) * 128 + (ks + (lane >> 4) * 8) * 2);
            uint32_t ad = sb + AQ_H + SWZ(offA);
            ldsm4(ah, ad);
            ldsm4(al, ad + 16384);
            #pragma unroll
            for (int nt2 = 0; nt2 < 4; nt2++) {
                uint32_t offB = (uint32_t)((wn + nt2 * 16 + ((lane >> 4) << 3) + (lane & 7)) * 128
                              + (ks + ((lane >> 3) & 1) * 8) * 2);
                uint32_t bd = kbuf + SWZ(offB);
                uint32_t t[4];
                ldsm4(t, bd);
                bhf[nt2*2][0]=t[0]; bhf[nt2*2][1]=t[1]; bhf[nt2*2+1][0]=t[2]; bhf[nt2*2+1][1]=t[3];
                ldsm4(t, bd + 16384);
                blf[nt2*2][0]=t[0]; blf[nt2*2][1]=t[1]; blf[nt2*2+1][0]=t[2]; blf[nt2*2+1][1]=t[3];
            }
            #pragma unroll
            for (int nt = 0; nt < 8; nt++) {
                mma16816(s[nt], ah, bhf[nt]);
                mma16816(s[nt], ah, blf[nt]);
                mma16816(s[nt], al, bhf[nt]);
            }
        }

        // ---- exp in regs, rowsum, unnormalized weights store ----
        int row0 = q0 + wm + gid;
        #pragma unroll
        for (int nt = 0; nt < 8; nt++) {
            s[nt][0] = __expf(s[nt][0]);
            s[nt][1] = __expf(s[nt][1]);
            s[nt][2] = __expf(s[nt][2]);
            s[nt][3] = __expf(s[nt][3]);
            rsum[0] += s[nt][0] + s[nt][1];
            rsum[1] += s[nt][2] + s[nt][3];
            int col = kt * 128 + wn + nt * 8 + tid4 * 2;
            *(float2*)&wbase[(size_t)row0 * SEQ + col]       = make_float2(s[nt][0], s[nt][1]);
            *(float2*)&wbase[(size_t)(row0 + 8) * SEQ + col] = make_float2(s[nt][2], s[nt][3]);
        }

        // ---- pv += E(this warp's k-slice) x V ----
        #pragma unroll
        for (int j = 0; j < 4; j++) {
            uint32_t eh[4], el[4];
            eh[0] = pack2f (s[2*j][0],   s[2*j][1]);
            eh[1] = pack2f (s[2*j][2],   s[2*j][3]);
            eh[2] = pack2f (s[2*j+1][0], s[2*j+1][1]);
            eh[3] = pack2f (s[2*j+1][2], s[2*j+1][3]);
            el[0] = pack2lo(s[2*j][0],   s[2*j][1]);
            el[1] = pack2lo(s[2*j][2],   s[2*j][3]);
            el[2] = pack2lo(s[2*j+1][0], s[2*j+1][1]);
            el[3] = pack2lo(s[2*j+1][2], s[2*j+1][3]);

            uint32_t vh[8][2], vl[8][2];
            #pragma unroll
            for (int dt2 = 0; dt2 < 4; dt2++) {
                int vr = dt2 * 16 + ((lane >> 4) << 3) + (lane & 7);
                int c16 = (wn * 2 + j * 32 + ((lane >> 3) & 1) * 16) >> 4;
                uint32_t vad = vbuf + vswz(vr, c16);
                uint32_t t[4];
                ldsm4(t, vad);
                vh[dt2*2][0]=t[0]; vh[dt2*2][1]=t[1]; vh[dt2*2+1][0]=t[2]; vh[dt2*2+1][1]=t[3];
                ldsm4(t, vad + 16384);
                vl[dt2*2][0]=t[0]; vl[dt2*2][1]=t[1]; vl[dt2*2+1][0]=t[2]; vl[dt2*2+1][1]=t[3];
            }
            #pragma unroll
            for (int nt = 0; nt < 8; nt++) {
                mma16816(pv[nt], eh, vh[nt]);
                mma16816(pv[nt], eh, vl[nt]);
                mma16816(pv[nt], el, vh[nt]);
            }
        }
    }
    __syncthreads();

    // ---- rowsum reduce + cross-warp PV exchange ----
    float* red   = (float*)(smem + ARED);     // [128][2]
    float* rinvs = (float*)(smem + ARINV);    // [128]
    float* xch   = (float*)(smem + AKB);      // reuse K buf0: 8x32x32 floats = 32KB
    #pragma unroll
    for (int i = 0; i < 2; i++) {
        rsum[i] += __shfl_xor_sync(0xFFFFFFFFu, rsum[i], 1);
        rsum[i] += __shfl_xor_sync(0xFFFFFFFFu, rsum[i], 2);
    }
    if (tid4 == 0) {
        red[(wm + 0 + gid) * 2 + (w & 1)] = rsum[0];
        red[(wm + 8 + gid) * 2 + (w & 1)] = rsum[1];
    }
    if (w & 1) {
        #pragma unroll
        for (int nt = 0; nt < 8; nt++)
            #pragma unroll
            for (int i = 0; i < 4; i++)
                xch[((w >> 1) * 32 + lane) * 32 + nt * 4 + i] = pv[nt][i];
    }
    __syncthreads();
    if (tid < 128) {
        float ri = 1.0f / (red[tid * 2] + red[tid * 2 + 1]);
        rinvs[tid] = ri;
        g_rinv[(size_t)bh * SEQ + q0 + tid] = ri;
    }
    __syncthreads();

    if (!(w & 1)) {
        #pragma unroll
        for (int nt = 0; nt < 8; nt++)
            #pragma unroll
            for (int i = 0; i < 4; i++)
                pv[nt][i] += xch[((w >> 1) * 32 + lane) * 32 + nt * 4 + i];

        int b = bh >> 4, h = bh & 15;
        #pragma unroll
        for (int rh = 0; rh < 2; rh++) {
            int row = wm + rh * 8 + gid;
            float ri = rinvs[row];
            #pragma unroll
            for (int nt = 0; nt < 8; nt++) {
                float v0 = pv[nt][rh * 2 + 0] * ri;
                float v1 = pv[nt][rh * 2 + 1] * ri;
                int d = nt * 8 + tid4 * 2;
                __nv_bfloat16 h0, l0, h1, l1;
                split2(v0, h0, l0); split2(v1, h1, l1);
                size_t dst = ((size_t)(b * SEQ + q0 + row)) * DM + h * DH + d;
                *(uint32_t*)&g_attH[dst] = pack2(h0, h1);
                *(uint32_t*)&g_attL[dst] = pack2(l0, l1);
            }
        }
    }
}

// ---------------------------------------------------------------------------
// Normalize weights in place (streaming)
// ---------------------------------------------------------------------------
__global__ void norm_kernel(float* __restrict__ w) {
    size_t f4 = (size_t)blockIdx.x * blockDim.x + threadIdx.x;
    size_t fidx = f4 * 4;
    int rowi = (int)(fidx >> 11);
    float r = g_rinv[rowi];
    float4 v = *(float4*)&w[fidx];
    v.x *= r; v.y *= r; v.z *= r; v.w *= r;
    *(float4*)&w[fidx] = v;
}

// ---------------------------------------------------------------------------
extern "C" void kernel_launch(void* const* d_in, const int* in_sizes, int n_in,
                              void* d_out, int out_size) {
    const float* x  = (const float*)d_in[0];
    const float* wq = (const float*)d_in[1];
    const float* bq = (const float*)d_in[2];
    const float* wk = (const float*)d_in[3];
    const float* bk = (const float*)d_in[4];
    const float* wv = (const float*)d_in[5];
    const float* bv = (const float*)d_in[6];
    const float* wo = (const float*)d_in[7];
    const float* bo = (const float*)d_in[8];

    float* out     = (float*)d_out;
    float* weights = out + (size_t)M_TOT * DM;

    static cudaStream_t s2 = nullptr;
    static cudaEvent_t evFork = nullptr, evJoin = nullptr;
    if (!s2) {
        cudaStreamCreateWithFlags(&s2, cudaStreamNonBlocking);
        cudaEventCreateWithFlags(&evFork, cudaEventDisableTiming);
        cudaEventCreateWithFlags(&evJoin, cudaEventDisableTiming);
        cudaFuncSetAttribute(proj_qkv_kernel, cudaFuncAttributeMaxDynamicSharedMemorySize, PROJ_SMEM);
        cudaFuncSetAttribute(proj_o_kernel,   cudaFuncAttributeMaxDynamicSharedMemorySize, PROJ_SMEM);
        cudaFuncSetAttribute(attn_tc_kernel,  cudaFuncAttributeMaxDynamicSharedMemorySize, ATTN_SMEM);
    }

    prep_kernel<<<8192, 256>>>(x, wq, wk, wv, wo);

    proj_qkv_kernel<<<dim3(3 * DM / 128, M_TOT / 128), 256, PROJ_SMEM>>>(bq, bk, bv);

    attn_tc_kernel<<<dim3(SEQ / 128, BH_TOT), 512, ATTN_SMEM>>>(weights);

    // Fork: norm (DRAM-bound) concurrent with proj_o (tensor-bound)
    cudaEventRecord(evFork, 0);
    cudaStreamWaitEvent(s2, evFork, 0);

    size_t nf4 = (size_t)BH_TOT * SEQ * SEQ / 4;
    norm_kernel<<<(unsigned)(nf4 / 256), 256, 0, s2>>>(weights);

    proj_o_kernel<<<dim3(DM / 128, M_TOT / 128), 256, PROJ_SMEM>>>(bo, out);

    cudaEventRecord(evJoin, s2);
    cudaStreamWaitEvent(0, evJoin, 0);
}

// round 12
// speedup vs baseline: 1.0496x; 1.0456x over previous
#include <cuda_runtime.h>
#include <cuda_bf16.h>
#include <cstdint>

#define BATCH 2
#define SEQ   2048
#define DM    1024
#define NH    16
#define DH    64
#define M_TOT (BATCH*SEQ)   // 4096
#define BH_TOT (BATCH*NH)   // 32

// ---------------------------------------------------------------------------
// Scratch (__device__ globals; allocation-free rule)
// ---------------------------------------------------------------------------
__device__ __nv_bfloat16 g_xH[M_TOT*DM],  g_xL[M_TOT*DM];
__device__ __nv_bfloat16 g_WtH[3*DM*DM],  g_WtL[3*DM*DM];      // [n][k], q|k|v
__device__ __nv_bfloat16 g_WoTH[DM*DM],   g_WoTL[DM*DM];       // [n][k]
__device__ __nv_bfloat16 g_QH[BH_TOT*SEQ*DH], g_QL[BH_TOT*SEQ*DH];
__device__ __nv_bfloat16 g_KH[BH_TOT*SEQ*DH], g_KL[BH_TOT*SEQ*DH];
__device__ __nv_bfloat16 g_VtH[BH_TOT*DH*SEQ], g_VtL[BH_TOT*DH*SEQ]; // [bh][d][s]
__device__ __nv_bfloat16 g_attH[M_TOT*DM], g_attL[M_TOT*DM];
__device__ float g_rinv[BH_TOT*SEQ];

// ---------------------------------------------------------------------------
// Helpers
// ---------------------------------------------------------------------------
__device__ __forceinline__ uint32_t smem_u32(const void* p) {
    uint32_t a;
    asm("{ .reg .u64 t; cvta.to.shared.u64 t, %1; cvt.u32.u64 %0, t; }" : "=r"(a) : "l"(p));
    return a;
}
__device__ __forceinline__ void ldsm4(uint32_t* r, uint32_t a) {
    asm volatile("ldmatrix.sync.aligned.m8n8.x4.shared.b16 {%0,%1,%2,%3}, [%4];"
        : "=r"(r[0]), "=r"(r[1]), "=r"(r[2]), "=r"(r[3]) : "r"(a));
}
__device__ __forceinline__ void mma16816(float* d, const uint32_t* a, const uint32_t* b) {
    asm volatile("mma.sync.aligned.m16n8k16.row.col.f32.bf16.bf16.f32 "
        "{%0,%1,%2,%3},{%4,%5,%6,%7},{%8,%9},{%0,%1,%2,%3};"
        : "+f"(d[0]), "+f"(d[1]), "+f"(d[2]), "+f"(d[3])
        : "r"(a[0]), "r"(a[1]), "r"(a[2]), "r"(a[3]), "r"(b[0]), "r"(b[1]));
}
#define CPA16(s, g) asm volatile("cp.async.ca.shared.global [%0], [%1], 16;" :: "r"(s), "l"(g) : "memory")
#define CPA_COMMIT() asm volatile("cp.async.commit_group;" ::: "memory")
#define CPA_WAIT0()  asm volatile("cp.async.wait_group 0;" ::: "memory")
#define CPA_WAIT1()  asm volatile("cp.async.wait_group 1;" ::: "memory")

__device__ __forceinline__ void split2(float v, __nv_bfloat16& h, __nv_bfloat16& l) {
    h = __float2bfloat16(v);
    l = __float2bfloat16(v - __bfloat162float(h));
}
__device__ __forceinline__ uint32_t pack2(__nv_bfloat16 a, __nv_bfloat16 b) {
    __nv_bfloat162 t; t.x = a; t.y = b;
    return *reinterpret_cast<uint32_t*>(&t);
}
__device__ __forceinline__ uint32_t pack2f(float a, float b) {
    __nv_bfloat162 t; t.x = __float2bfloat16(a); t.y = __float2bfloat16(b);
    return *reinterpret_cast<uint32_t*>(&t);
}
__device__ __forceinline__ uint32_t pack2lo(float a, float b) {
    __nv_bfloat16 ha = __float2bfloat16(a), hb = __float2bfloat16(b);
    __nv_bfloat162 t;
    t.x = __float2bfloat16(a - __bfloat162float(ha));
    t.y = __float2bfloat16(b - __bfloat162float(hb));
    return *reinterpret_cast<uint32_t*>(&t);
}

// ---------------------------------------------------------------------------
// Prep (merged): blocks 0..4095 split x; blocks 4096..8191 transpose+split W.
// ---------------------------------------------------------------------------
__global__ void prep_kernel(const float* __restrict__ x,
                            const float* __restrict__ wq, const float* __restrict__ wk,
                            const float* __restrict__ wv, const float* __restrict__ wo) {
    __shared__ float t[32][33];
    int bx = blockIdx.x, tid = threadIdx.x;
    if (bx < 4096) {
        size_t i4 = (size_t)bx * 256 + tid;
        float4 v = *(const float4*)&x[i4 * 4];
        __nv_bfloat16 h[4], l[4];
        split2(v.x, h[0], l[0]); split2(v.y, h[1], l[1]);
        split2(v.z, h[2], l[2]); split2(v.w, h[3], l[3]);
        *(uint2*)&g_xH[i4 * 4] = *(uint2*)h;
        *(uint2*)&g_xL[i4 * 4] = *(uint2*)l;
        return;
    }
    int idx = bx - 4096;
    int which = idx >> 10; idx &= 1023;
    const float* W = (which == 0) ? wq : (which == 1) ? wk : (which == 2) ? wv : wo;
    __nv_bfloat16* H = (which < 3) ? g_WtH + (size_t)which * DM * DM : g_WoTH;
    __nv_bfloat16* L = (which < 3) ? g_WtL + (size_t)which * DM * DM : g_WoTL;
    int x0 = (idx & 31) * 32, y0 = (idx >> 5) * 32;
    int tx = tid & 31, ty = tid >> 5;
    #pragma unroll
    for (int r = 0; r < 4; r++)
        t[ty + r * 8][tx] = W[(size_t)(y0 + ty + r * 8) * DM + x0 + tx];
    __syncthreads();
    #pragma unroll
    for (int r = 0; r < 4; r++) {
        float v = t[tx][ty + r * 8];
        __nv_bfloat16 h, l; split2(v, h, l);
        size_t dst = (size_t)(x0 + ty + r * 8) * DM + y0 + tx;
        H[dst] = h; L[dst] = l;
    }
}

// ---------------------------------------------------------------------------
// Projection GEMM mainloop: 2-stage cp.async double-buffered pipeline.
// ---------------------------------------------------------------------------
#define PS_AH 0
#define PS_AL 18432
#define PS_BH 36864
#define PS_BL 55296
#define PS_STAGE 73728
#define PROJ_SMEM (2 * PS_STAGE)

__device__ __forceinline__ void proj_prefetch(uint32_t sbs,
    const __nv_bfloat16* __restrict__ Ah, const __nv_bfloat16* __restrict__ Al,
    const __nv_bfloat16* __restrict__ Bh, const __nv_bfloat16* __restrict__ Bl,
    int m0, int n0, int k0, int tid) {
    #pragma unroll
    for (int e = 0; e < 4; e++) {
        int i = tid + e * 256;
        int row = i >> 3, cc = i & 7;
        size_t ga = (size_t)(m0 + row) * DM + k0 + cc * 8;
        size_t gb = (size_t)(n0 + row) * DM + k0 + cc * 8;
        uint32_t so = sbs + row * 144 + cc * 16;
        CPA16(so + PS_AH, Ah + ga);
        CPA16(so + PS_AL, Al + ga);
        CPA16(so + PS_BH, Bh + gb);
        CPA16(so + PS_BL, Bl + gb);
    }
}

__device__ __forceinline__ void gemm_ml(char* smem,
    const __nv_bfloat16* __restrict__ Ah, const __nv_bfloat16* __restrict__ Al,
    const __nv_bfloat16* __restrict__ Bh, const __nv_bfloat16* __restrict__ Bl,
    int m0, int n0, float (&c)[2][8][4]) {
    uint32_t sb0 = smem_u32(smem);
    int tid = threadIdx.x, lane = tid & 31, w = tid >> 5;
    int wm = (w >> 1) * 32, wn = (w & 1) * 64;

    proj_prefetch(sb0, Ah, Al, Bh, Bl, m0, n0, 0, tid);
    CPA_COMMIT();

    for (int s = 0; s < 16; s++) {
        if (s + 1 < 16) {
            proj_prefetch(sb0 + ((s + 1) & 1) * PS_STAGE, Ah, Al, Bh, Bl,
                          m0, n0, (s + 1) * 64, tid);
            CPA_COMMIT();
            CPA_WAIT1();
        } else {
            CPA_WAIT0();
        }
        __syncthreads();
        uint32_t sb = sb0 + (s & 1) * PS_STAGE;
        #pragma unroll
        for (int ks = 0; ks < 64; ks += 16) {
            uint32_t ah[2][4], al[2][4], bhf[8][2], blf[8][2];
            #pragma unroll
            for (int mt = 0; mt < 2; mt++) {
                uint32_t ad = sb + PS_AH + (uint32_t)(wm + mt * 16 + (lane & 15)) * 144
                            + (ks + (lane >> 4) * 8) * 2;
                ldsm4(ah[mt], ad);
                ldsm4(al[mt], ad + (PS_AL - PS_AH));
            }
            #pragma unroll
            for (int nt2 = 0; nt2 < 4; nt2++) {
                uint32_t bd = sb + PS_BH
                            + (uint32_t)(wn + nt2 * 16 + ((lane >> 4) << 3) + (lane & 7)) * 144
                            + (ks + ((lane >> 3) & 1) * 8) * 2;
                uint32_t t[4];
                ldsm4(t, bd);
                bhf[nt2*2][0]=t[0]; bhf[nt2*2][1]=t[1]; bhf[nt2*2+1][0]=t[2]; bhf[nt2*2+1][1]=t[3];
                ldsm4(t, bd + (PS_BL - PS_BH));
                blf[nt2*2][0]=t[0]; blf[nt2*2][1]=t[1]; blf[nt2*2+1][0]=t[2]; blf[nt2*2+1][1]=t[3];
            }
            #pragma unroll
            for (int mt = 0; mt < 2; mt++)
                #pragma unroll
                for (int nt = 0; nt < 8; nt++) {
                    mma16816(c[mt][nt], ah[mt], bhf[nt]);
                    mma16816(c[mt][nt], ah[mt], blf[nt]);
                    mma16816(c[mt][nt], al[mt], bhf[nt]);
                }
        }
        __syncthreads();
    }
}

// ---------------------------------------------------------------------------
// QKV projection
// ---------------------------------------------------------------------------
__global__ void __launch_bounds__(256, 1) proj_qkv_kernel(
    const float* __restrict__ bq, const float* __restrict__ bk, const float* __restrict__ bv) {
    extern __shared__ char smem[];
    int n0 = blockIdx.x * 128;
    int m0 = blockIdx.y * 128;
    float c[2][8][4] = {};
    gemm_ml(smem, g_xH, g_xL, g_WtH, g_WtL, m0, n0, c);

    int tid = threadIdx.x, lane = tid & 31, w = tid >> 5;
    int wm = (w >> 1) * 32, wn = (w & 1) * 64;
    int gid = lane >> 2, tid4 = lane & 3;
    int j = n0 >> 10, nb = n0 & 1023;
    const float* bias = (j == 0) ? bq : (j == 1) ? bk : bv;
    float scale = (j == 0) ? 0.125f : 1.0f;
    __nv_bfloat16* dH = (j == 0) ? g_QH : g_KH;
    __nv_bfloat16* dL = (j == 0) ? g_QL : g_KL;

    #pragma unroll
    for (int mt = 0; mt < 2; mt++)
        #pragma unroll
        for (int rh = 0; rh < 2; rh++) {
            int m = m0 + wm + mt * 16 + rh * 8 + gid;
            int b = m >> 11, s2 = m & (SEQ - 1);
            #pragma unroll
            for (int nt = 0; nt < 8; nt++) {
                int nl = nb + wn + nt * 8 + tid4 * 2;
                float v0 = (c[mt][nt][rh * 2 + 0] + bias[nl]) * scale;
                float v1 = (c[mt][nt][rh * 2 + 1] + bias[nl + 1]) * scale;
                __nv_bfloat16 h0, l0, h1, l1;
                split2(v0, h0, l0); split2(v1, h1, l1);
                int hh = nl >> 6, d = nl & 63;
                if (j < 2) {
                    size_t dst = (((size_t)(b * NH + hh)) * SEQ + s2) * DH + d;
                    *(uint32_t*)&dH[dst] = pack2(h0, h1);
                    *(uint32_t*)&dL[dst] = pack2(l0, l1);
                } else {
                    size_t dst = (((size_t)(b * NH + hh)) * DH + d) * SEQ + s2;
                    g_VtH[dst] = h0; g_VtH[dst + SEQ] = h1;
                    g_VtL[dst] = l0; g_VtL[dst + SEQ] = l1;
                }
            }
        }
}

// ---------------------------------------------------------------------------
// Output projection (standalone)
// ---------------------------------------------------------------------------
__global__ void __launch_bounds__(256, 1) proj_o_kernel(
    const float* __restrict__ bo, float* __restrict__ out) {
    extern __shared__ char smem[];
    int n0 = blockIdx.x * 128;
    int m0 = blockIdx.y * 128;
    float c[2][8][4] = {};
    gemm_ml(smem, g_attH, g_attL, g_WoTH, g_WoTL, m0, n0, c);

    int tid = threadIdx.x, lane = tid & 31, w = tid >> 5;
    int wm = (w >> 1) * 32, wn = (w & 1) * 64;
    int gid = lane >> 2, tid4 = lane & 3;

    #pragma unroll
    for (int mt = 0; mt < 2; mt++)
        #pragma unroll
        for (int rh = 0; rh < 2; rh++) {
            int m = m0 + wm + mt * 16 + rh * 8 + gid;
            #pragma unroll
            for (int nt = 0; nt < 8; nt++) {
                int n = n0 + wn + nt * 8 + tid4 * 2;
                float2 o;
                o.x = c[mt][nt][rh * 2 + 0] + bo[n];
                o.y = c[mt][nt][rh * 2 + 1] + bo[n + 1];
                *(float2*)&out[(size_t)m * DM + n] = o;
            }
        }
}

// ---------------------------------------------------------------------------
// Attention (R9 winner + cp.async staggered K/V prefetch):
// 256 threads, q-tile 64, warp m16 x n64 (4m x 2n), register-E, occ 2.
// Groups: GK(kt) committed after S(kt-1); GV(kt) committed after PV(kt-1).
// Top-of-loop wait_group 1 releases K; pre-PV wait_group 1 releases V.
// ---------------------------------------------------------------------------
#define AT_QH 0
#define AT_QL 9216
#define AT_KH 18432
#define AT_KL 36864
#define AT_VH 55296
#define AT_VL 72704
#define AT_RED 90112
#define AT_RINV 90624
#define ATTN_SMEM 90880

__device__ __forceinline__ void attn_load_K(uint32_t sb, int bh, int kt, int tid) {
    #pragma unroll
    for (int e = 0; e < 4; e++) {
        int i = tid + e * 256;
        int row = i >> 3, c = i & 7;
        size_t g = ((size_t)bh * SEQ + kt * 128 + row) * DH + c * 8;
        uint32_t so = sb + AT_KH + row * 144 + c * 16;
        CPA16(so, g_KH + g);
        CPA16(so + (AT_KL - AT_KH), g_KL + g);
    }
}
__device__ __forceinline__ void attn_load_V(uint32_t sb, int bh, int kt, int tid) {
    #pragma unroll
    for (int e = 0; e < 4; e++) {
        int i = tid + e * 256;
        int row = i >> 4, c = i & 15;
        size_t g = ((size_t)bh * DH + row) * SEQ + kt * 128 + c * 8;
        uint32_t so = sb + AT_VH + row * 272 + c * 16;
        CPA16(so, g_VtH + g);
        CPA16(so + (AT_VL - AT_VH), g_VtL + g);
    }
}

__global__ void __launch_bounds__(256, 2) attn_tc_kernel(float* __restrict__ weights) {
    extern __shared__ char smem[];
    uint32_t sb = smem_u32(smem);
    int tid = threadIdx.x, lane = tid & 31, w = tid >> 5;
    int wg = w >> 1;
    int wm = wg * 16;
    int wn = (w & 1) * 64;
    int gid = lane >> 2, tid4 = lane & 3;
    int bh = blockIdx.y, q0 = blockIdx.x * 64;

    // preamble: Q + K(0) as group A, V(0) as group B
    #pragma unroll
    for (int e = 0; e < 2; e++) {
        int i = tid + e * 256;
        int row = i >> 3, c = i & 7;
        size_t g = ((size_t)bh * SEQ + q0 + row) * DH + c * 8;
        uint32_t so = sb + AT_QH + row * 144 + c * 16;
        CPA16(so, g_QH + g);
        CPA16(so + (AT_QL - AT_QH), g_QL + g);
    }
    attn_load_K(sb, bh, 0, tid);
    CPA_COMMIT();
    attn_load_V(sb, bh, 0, tid);
    CPA_COMMIT();

    float* wbase = weights + (size_t)bh * SEQ * SEQ;
    float pv[8][4] = {};
    float rsum[2] = {};

    for (int kt = 0; kt < SEQ / 128; kt++) {
        CPA_WAIT1();                 // Q + K(kt) arrived (V(kt) may pend)
        __syncthreads();

        // ---- S = Q K^T (scale pre-folded into Q) ----
        float s[8][4] = {};
        #pragma unroll
        for (int ks = 0; ks < 64; ks += 16) {
            uint32_t ah[4], al[4], bhf[8][2], blf[8][2];
            uint32_t ad = sb + AT_QH + (uint32_t)(wm + (lane & 15)) * 144
                        + (ks + (lane >> 4) * 8) * 2;
            ldsm4(ah, ad);
            ldsm4(al, ad + (AT_QL - AT_QH));
            #pragma unroll
            for (int nt2 = 0; nt2 < 4; nt2++) {
                uint32_t bd = sb + AT_KH
                            + (uint32_t)(wn + nt2 * 16 + ((lane >> 4) << 3) + (lane & 7)) * 144
                            + (ks + ((lane >> 3) & 1) * 8) * 2;
                uint32_t t[4];
                ldsm4(t, bd);
                bhf[nt2*2][0]=t[0]; bhf[nt2*2][1]=t[1]; bhf[nt2*2+1][0]=t[2]; bhf[nt2*2+1][1]=t[3];
                ldsm4(t, bd + (AT_KL - AT_KH));
                blf[nt2*2][0]=t[0]; blf[nt2*2][1]=t[1]; blf[nt2*2+1][0]=t[2]; blf[nt2*2+1][1]=t[3];
            }
            #pragma unroll
            for (int nt = 0; nt < 8; nt++) {
                mma16816(s[nt], ah, bhf[nt]);
                mma16816(s[nt], ah, blf[nt]);
                mma16816(s[nt], al, bhf[nt]);
            }
        }
        __syncthreads();             // all warps done reading K smem
        if (kt + 1 < SEQ / 128) {
            attn_load_K(sb, bh, kt + 1, tid);   // GK(kt+1): lands under exp+PV
            CPA_COMMIT();
        }

        // ---- exp in regs, rowsum, unnormalized weights store ----
        int row0 = q0 + wm + gid;
        #pragma unroll
        for (int nt = 0; nt < 8; nt++) {
            s[nt][0] = __expf(s[nt][0]);
            s[nt][1] = __expf(s[nt][1]);
            s[nt][2] = __expf(s[nt][2]);
            s[nt][3] = __expf(s[nt][3]);
            rsum[0] += s[nt][0] + s[nt][1];
            rsum[1] += s[nt][2] + s[nt][3];
            int col = kt * 128 + wn + nt * 8 + tid4 * 2;
            *(float2*)&wbase[(size_t)row0 * SEQ + col]       = make_float2(s[nt][0], s[nt][1]);
            *(float2*)&wbase[(size_t)(row0 + 8) * SEQ + col] = make_float2(s[nt][2], s[nt][3]);
        }

        if (kt + 1 < SEQ / 128) { CPA_WAIT1(); } else { CPA_WAIT0(); }  // V(kt) arrived
        __syncthreads();

        // ---- pv += E(this warp's k-slice) x V ----
        #pragma unroll
        for (int j = 0; j < 4; j++) {
            uint32_t eh[4], el[4];
            eh[0] = pack2f (s[2*j][0],   s[2*j][1]);
            eh[1] = pack2f (s[2*j][2],   s[2*j][3]);
            eh[2] = pack2f (s[2*j+1][0], s[2*j+1][1]);
            eh[3] = pack2f (s[2*j+1][2], s[2*j+1][3]);
            el[0] = pack2lo(s[2*j][0],   s[2*j][1]);
            el[1] = pack2lo(s[2*j][2],   s[2*j][3]);
            el[2] = pack2lo(s[2*j+1][0], s[2*j+1][1]);
            el[3] = pack2lo(s[2*j+1][2], s[2*j+1][3]);

            uint32_t vh[8][2], vl[8][2];
            #pragma unroll
            for (int dt2 = 0; dt2 < 4; dt2++) {
                uint32_t bd = sb + AT_VH
                            + (uint32_t)(dt2 * 16 + ((lane >> 4) << 3) + (lane & 7)) * 272
                            + (wn + j * 16 + ((lane >> 3) & 1) * 8) * 2;
                uint32_t t[4];
                ldsm4(t, bd);
                vh[dt2*2][0]=t[0]; vh[dt2*2][1]=t[1]; vh[dt2*2+1][0]=t[2]; vh[dt2*2+1][1]=t[3];
                ldsm4(t, bd + (AT_VL - AT_VH));
                vl[dt2*2][0]=t[0]; vl[dt2*2][1]=t[1]; vl[dt2*2+1][0]=t[2]; vl[dt2*2+1][1]=t[3];
            }
            #pragma unroll
            for (int nt = 0; nt < 8; nt++) {
                mma16816(pv[nt], eh, vh[nt]);
                mma16816(pv[nt], eh, vl[nt]);
                mma16816(pv[nt], el, vh[nt]);
            }
        }
        __syncthreads();             // all warps done reading V smem
        if (kt + 1 < SEQ / 128) {
            attn_load_V(sb, bh, kt + 1, tid);   // GV(kt+1): lands under next S+exp
            CPA_COMMIT();
        }
    }
    __syncthreads();

    // ---- rowsum reduce ----
    float* red   = (float*)(smem + AT_RED);
    float* rinvs = (float*)(smem + AT_RINV);
    #pragma unroll
    for (int i = 0; i < 2; i++) {
        rsum[i] += __shfl_xor_sync(0xFFFFFFFFu, rsum[i], 1);
        rsum[i] += __shfl_xor_sync(0xFFFFFFFFu, rsum[i], 2);
    }
    if (tid4 == 0) {
        red[(wm + 0 + gid) * 2 + (w & 1)] = rsum[0];
        red[(wm + 8 + gid) * 2 + (w & 1)] = rsum[1];
    }
    __syncthreads();
    if (tid < 64) {
        float ri = 1.0f / (red[tid * 2] + red[tid * 2 + 1]);
        rinvs[tid] = ri;
        g_rinv[(size_t)bh * SEQ + q0 + tid] = ri;
    }

    // ---- cross-warp PV add ----
    float* xch = (float*)(smem + AT_KH);
    if (w & 1) {
        #pragma unroll
        for (int nt = 0; nt < 8; nt++)
            #pragma unroll
            for (int i = 0; i < 4; i++)
                xch[(wg * 32 + lane) * 32 + nt * 4 + i] = pv[nt][i];
    }
    __syncthreads();
    if (!(w & 1)) {
        #pragma unroll
        for (int nt = 0; nt < 8; nt++)
            #pragma unroll
            for (int i = 0; i < 4; i++)
                pv[nt][i] += xch[(wg * 32 + lane) * 32 + nt * 4 + i];

        int b = bh >> 4, h = bh & 15;
        #pragma unroll
        for (int rh = 0; rh < 2; rh++) {
            int row = wm + rh * 8 + gid;
            float ri = rinvs[row];
            #pragma unroll
            for (int nt = 0; nt < 8; nt++) {
                float v0 = pv[nt][rh * 2 + 0] * ri;
                float v1 = pv[nt][rh * 2 + 1] * ri;
                int d = nt * 8 + tid4 * 2;
                __nv_bfloat16 h0, l0, h1, l1;
                split2(v0, h0, l0); split2(v1, h1, l1);
                size_t dst = ((size_t)(b * SEQ + q0 + row)) * DM + h * DH + d;
                *(uint32_t*)&g_attH[dst] = pack2(h0, h1);
                *(uint32_t*)&g_attL[dst] = pack2(l0, l1);
            }
        }
    }
}

// ---------------------------------------------------------------------------
// Normalize weights in place (streaming)
// ---------------------------------------------------------------------------
__global__ void norm_kernel(float* __restrict__ w) {
    size_t f4 = (size_t)blockIdx.x * blockDim.x + threadIdx.x;
    size_t fidx = f4 * 4;
    int rowi = (int)(fidx >> 11);
    float r = g_rinv[rowi];
    float4 v = *(float4*)&w[fidx];
    v.x *= r; v.y *= r; v.z *= r; v.w *= r;
    *(float4*)&w[fidx] = v;
}

// ---------------------------------------------------------------------------
extern "C" void kernel_launch(void* const* d_in, const int* in_sizes, int n_in,
                              void* d_out, int out_size) {
    const float* x  = (const float*)d_in[0];
    const float* wq = (const float*)d_in[1];
    const float* bq = (const float*)d_in[2];
    const float* wk = (const float*)d_in[3];
    const float* bk = (const float*)d_in[4];
    const float* wv = (const float*)d_in[5];
    const float* bv = (const float*)d_in[6];
    const float* wo = (const float*)d_in[7];
    const float* bo = (const float*)d_in[8];

    float* out     = (float*)d_out;
    float* weights = out + (size_t)M_TOT * DM;

    static cudaStream_t s2 = nullptr;
    static cudaEvent_t evFork = nullptr, evJoin = nullptr;
    if (!s2) {
        cudaStreamCreateWithFlags(&s2, cudaStreamNonBlocking);
        cudaEventCreateWithFlags(&evFork, cudaEventDisableTiming);
        cudaEventCreateWithFlags(&evJoin, cudaEventDisableTiming);
        cudaFuncSetAttribute(proj_qkv_kernel, cudaFuncAttributeMaxDynamicSharedMemorySize, PROJ_SMEM);
        cudaFuncSetAttribute(proj_o_kernel,   cudaFuncAttributeMaxDynamicSharedMemorySize, PROJ_SMEM);
        cudaFuncSetAttribute(attn_tc_kernel,  cudaFuncAttributeMaxDynamicSharedMemorySize, ATTN_SMEM);
    }

    prep_kernel<<<8192, 256>>>(x, wq, wk, wv, wo);

    proj_qkv_kernel<<<dim3(3 * DM / 128, M_TOT / 128), 256, PROJ_SMEM>>>(bq, bk, bv);

    attn_tc_kernel<<<dim3(SEQ / 64, BH_TOT), 256, ATTN_SMEM>>>(weights);

    // Fork: norm (DRAM-bound) concurrent with proj_o (tensor-bound)
    cudaEventRecord(evFork, 0);
    cudaStreamWaitEvent(s2, evFork, 0);

    size_t nf4 = (size_t)BH_TOT * SEQ * SEQ / 4;
    norm_kernel<<<(unsigned)(nf4 / 256), 256, 0, s2>>>(weights);

    proj_o_kernel<<<dim3(DM / 128, M_TOT / 128), 256, PROJ_SMEM>>>(bo, out);

    cudaEventRecord(evJoin, s2);
    cudaStreamWaitEvent(0, evJoin, 0);
}